// round 14
// baseline (speedup 1.0000x reference)
#include <cuda_runtime.h>
#include <cuda_bf16.h>
#include <cstdint>

// Problem constants
#define BB 32
#define NS 262144
#define HH 256
#define WW 256
#define HWSZ (HH * WW)

constexpr int SEGS = 16;

// Per-(batch, segment) partial bounds: x = xmin, y = xmax, z = ymin, w = ymax.
__device__ float4 g_part[BB][SEGS];
// Per-batch completion counters (zero-init; reset to zero every run by the
// last finishing block, so graph replays are deterministic).
__device__ int g_scat_done[BB];
__device__ int g_mul_done[BB];

// K1: grid = (SEGS, BB) = 512 blocks. Partial min/max + zero out-slice.
__global__ __launch_bounds__(256) void minmax_kernel(const float* __restrict__ spatial,
                                                     float4* __restrict__ out4) {
    const int b = blockIdx.y;
    const int seg_elems = HWSZ / SEGS;                 // 4096 floats
    const float* base = spatial + (size_t)b * 2 * HWSZ + (size_t)blockIdx.x * seg_elems;
    const float4* vx = reinterpret_cast<const float4*>(base);
    const float4* vy = reinterpret_cast<const float4*>(base + HWSZ);

    float4 ax[4], ay[4];
    #pragma unroll
    for (int j = 0; j < 4; j++) ax[j] = vx[threadIdx.x + j * 256];
    #pragma unroll
    for (int j = 0; j < 4; j++) ay[j] = vy[threadIdx.x + j * 256];

    // Zero this block's slice of the output field (4096 floats / block).
    {
        const size_t blk = (size_t)b * SEGS + blockIdx.x;
        float4* oz = out4 + blk * 1024;
        const float4 z = make_float4(0.f, 0.f, 0.f, 0.f);
        #pragma unroll
        for (int j = 0; j < 4; j++) oz[threadIdx.x + j * 256] = z;
    }

    float xmn = 3.4e38f, xmx = -3.4e38f, ymn = 3.4e38f, ymx = -3.4e38f;
    #pragma unroll
    for (int j = 0; j < 4; j++) {
        xmn = fminf(xmn, fminf(fminf(ax[j].x, ax[j].y), fminf(ax[j].z, ax[j].w)));
        xmx = fmaxf(xmx, fmaxf(fmaxf(ax[j].x, ax[j].y), fmaxf(ax[j].z, ax[j].w)));
        ymn = fminf(ymn, fminf(fminf(ay[j].x, ay[j].y), fminf(ay[j].z, ay[j].w)));
        ymx = fmaxf(ymx, fmaxf(fmaxf(ay[j].x, ay[j].y), fmaxf(ay[j].z, ay[j].w)));
    }

    #pragma unroll
    for (int off = 16; off > 0; off >>= 1) {
        xmn = fminf(xmn, __shfl_xor_sync(0xFFFFFFFFu, xmn, off));
        xmx = fmaxf(xmx, __shfl_xor_sync(0xFFFFFFFFu, xmx, off));
        ymn = fminf(ymn, __shfl_xor_sync(0xFFFFFFFFu, ymn, off));
        ymx = fmaxf(ymx, __shfl_xor_sync(0xFFFFFFFFu, ymx, off));
    }

    __shared__ float4 s[8];
    const int wid = threadIdx.x >> 5;
    const int lid = threadIdx.x & 31;
    if (lid == 0) s[wid] = make_float4(xmn, xmx, ymn, ymx);
    __syncthreads();
    if (threadIdx.x == 0) {
        float4 r = s[0];
        #pragma unroll
        for (int w = 1; w < 8; w++) {
            r.x = fminf(r.x, s[w].x);
            r.y = fmaxf(r.y, s[w].y);
            r.z = fminf(r.z, s[w].z);
            r.w = fmaxf(r.w, s[w].w);
        }
        g_part[b][blockIdx.x] = r;
    }
}

// K2: fused scatter + per-batch epilogue (out *= gia).
// grid = (CHUNKS, BB) batch-major; each batch's 64 blocks form a local barrier
// via g_scat_done[b], then each block multiplies one float4 per thread.
constexpr int TPB    = 256;
constexpr int IT     = 16;
constexpr int CHUNKS = NS / (TPB * IT);   // 64 blocks per batch

__global__ __launch_bounds__(TPB) void scatter_kernel(
    const float*  __restrict__ point_rates,
    const float2* __restrict__ coords,
    const float4* __restrict__ gia4,
    float4*       __restrict__ out4)
{
    const int b     = blockIdx.y;
    const int chunk = blockIdx.x;
    const int tid   = threadIdx.x;

    const float* pr = point_rates + (size_t)b * NS;
    float* ob = reinterpret_cast<float*>(out4) + (size_t)b * HWSZ;

    const int base = chunk * (TPB * IT) + tid;

    // Payload loads: inputs only — safe while minmax still runs (PDL).
    float2 c[IT];
    float  rate[IT];
    #pragma unroll
    for (int j = 0; j < IT; j++) c[j] = coords[base + j * TPB];
    #pragma unroll
    for (int j = 0; j < IT; j++) rate[j] = pr[base + j * TPB];

    // Wait for minmax grid completion (bounds written, out zeroed).
    cudaGridDependencySynchronize();

    // Bounds prologue: one warp reduces the SEGS(=16) partials.
    __shared__ float4 sb;
    if (tid < 32) {
        const int lid = tid;
        float xmn = 3.4e38f, xmx = -3.4e38f, ymn = 3.4e38f, ymx = -3.4e38f;
        if (lid < SEGS) {
            float4 p = g_part[b][lid];
            xmn = p.x; xmx = p.y; ymn = p.z; ymx = p.w;
        }
        #pragma unroll
        for (int off = 8; off > 0; off >>= 1) {
            xmn = fminf(xmn, __shfl_xor_sync(0xFFFFFFFFu, xmn, off));
            xmx = fmaxf(xmx, __shfl_xor_sync(0xFFFFFFFFu, xmx, off));
            ymn = fminf(ymn, __shfl_xor_sync(0xFFFFFFFFu, ymn, off));
            ymx = fmaxf(ymx, __shfl_xor_sync(0xFFFFFFFFu, ymx, off));
        }
        if (tid == 0) sb = make_float4(xmn, xmx, ymn, ymx);
    }
    __syncthreads();

    const float xmin = sb.x, xmax = sb.y, ymin = sb.z, ymax = sb.w;
    const float dx = __fsub_rn(xmax, xmin);
    const float dy = __fsub_rn(ymax, ymin);

    #pragma unroll
    for (int j = 0; j < IT; j++) {
        const bool iv = (c[j].x >= xmin) && (c[j].x <= xmax) &&
                        (c[j].y >= ymin) && (c[j].y <= ymax);
        // Match reference bit-exactly: strict IEEE rn sub/div/mul, then
        // round-half-even (== jnp.round) before clip.
        const float nx = __fdiv_rn(__fsub_rn(c[j].x, xmin), dx);
        const float ny = __fdiv_rn(__fsub_rn(c[j].y, ymin), dy);
        int px = __float2int_rn(__fmul_rn(nx, 255.0f));
        int py = __float2int_rn(__fmul_rn(ny, 255.0f));
        px = min(max(px, 0), WW - 1);
        py = min(max(py, 0), HH - 1);
        if (iv) {
            atomicAdd(&ob[py * WW + px], rate[j]);   // RED.ADD, no return
        }
    }

    // ---- per-batch barrier, then distributed epilogue: out *= gia ----------
    // This block's epilogue slice: one float4 per thread.
    const size_t eidx = (size_t)b * (HWSZ / 4) + (size_t)chunk * TPB + tid;

    // Prefetch gia slice (input; independent of the barrier).
    const float4 g = gia4[eidx];

    __syncthreads();                       // all threads' REDGs issued
    if (tid == 0) {
        __threadfence();                   // order REDGs before the counter
        atomicAdd(&g_scat_done[b], 1);
        // poll until all 64 blocks of this batch have arrived
        while (atomicAdd(&g_scat_done[b], 0) < CHUNKS) __nanosleep(128);
    }
    __syncthreads();
    __threadfence();                       // acquire: see peer blocks' adds

    float4 o = out4[eidx];
    o.x = __fmul_rn(o.x, g.x);
    o.y = __fmul_rn(o.y, g.y);
    o.z = __fmul_rn(o.z, g.z);
    o.w = __fmul_rn(o.w, g.w);
    out4[eidx] = o;

    // Reset counters for the next graph replay: last block of batch b cleans up.
    __syncthreads();
    if (tid == 0) {
        const int old = atomicAdd(&g_mul_done[b], 1);
        if (old == CHUNKS - 1) {
            g_scat_done[b] = 0;
            g_mul_done[b]  = 0;
            __threadfence();
        }
    }
}

extern "C" void kernel_launch(void* const* d_in, const int* in_sizes, int n_in,
                              void* d_out, int out_size)
{
    const float*  point_rates = (const float*)d_in[0];   // (B, NS)
    const float*  spatial     = (const float*)d_in[1];   // (B, 2, H, W)
    const float*  gia         = (const float*)d_in[2];   // (B, H, W)
    const float2* coords      = (const float2*)d_in[3];  // (NS, 2)
    float* out = (float*)d_out;                          // (B, 1, H, W)

    // K1: minmax partials + output zeroing
    dim3 mg(SEGS, BB);
    minmax_kernel<<<mg, 256>>>(spatial, (float4*)out);

    // K2: fused scatter + epilogue, PDL (payload loads overlap minmax drain)
    {
        cudaLaunchAttribute pdl[1];
        pdl[0].id = cudaLaunchAttributeProgrammaticStreamSerialization;
        pdl[0].val.programmaticStreamSerializationAllowed = 1;

        cudaLaunchConfig_t cfg = {};
        cfg.gridDim = dim3(CHUNKS, BB);    // batch-major: x fastest
        cfg.blockDim = dim3(TPB);
        cfg.stream = 0;
        cfg.attrs = pdl;
        cfg.numAttrs = 1;
        cudaLaunchKernelEx(&cfg, scatter_kernel,
                           point_rates, coords, (const float4*)gia, (float4*)out);
    }
}

// round 15
// speedup vs baseline: 1.6709x; 1.6709x over previous
#include <cuda_runtime.h>
#include <cuda_bf16.h>
#include <cstdint>

// Problem constants
#define BB 32
#define NS 262144
#define HH 256
#define WW 256
#define HWSZ (HH * WW)

constexpr int SEGS = 16;

// Per-(batch, segment) partial bounds: x = xmin, y = xmax, z = ymin, w = ymax.
__device__ float4 g_part[BB][SEGS];

// K1: grid = (SEGS, BB) = 512 blocks. Partial min/max + zero out-slice.
__global__ __launch_bounds__(256) void minmax_kernel(const float* __restrict__ spatial,
                                                     float4* __restrict__ out4) {
    const int b = blockIdx.y;
    const int seg_elems = HWSZ / SEGS;                 // 4096 floats
    const float* base = spatial + (size_t)b * 2 * HWSZ + (size_t)blockIdx.x * seg_elems;
    const float4* vx = reinterpret_cast<const float4*>(base);
    const float4* vy = reinterpret_cast<const float4*>(base + HWSZ);

    float4 ax[4], ay[4];
    #pragma unroll
    for (int j = 0; j < 4; j++) ax[j] = vx[threadIdx.x + j * 256];
    #pragma unroll
    for (int j = 0; j < 4; j++) ay[j] = vy[threadIdx.x + j * 256];

    // Zero this block's slice of the output field (4096 floats / block).
    {
        const size_t blk = (size_t)b * SEGS + blockIdx.x;
        float4* oz = out4 + blk * 1024;
        const float4 z = make_float4(0.f, 0.f, 0.f, 0.f);
        #pragma unroll
        for (int j = 0; j < 4; j++) oz[threadIdx.x + j * 256] = z;
    }

    float xmn = 3.4e38f, xmx = -3.4e38f, ymn = 3.4e38f, ymx = -3.4e38f;
    #pragma unroll
    for (int j = 0; j < 4; j++) {
        xmn = fminf(xmn, fminf(fminf(ax[j].x, ax[j].y), fminf(ax[j].z, ax[j].w)));
        xmx = fmaxf(xmx, fmaxf(fmaxf(ax[j].x, ax[j].y), fmaxf(ax[j].z, ax[j].w)));
        ymn = fminf(ymn, fminf(fminf(ay[j].x, ay[j].y), fminf(ay[j].z, ay[j].w)));
        ymx = fmaxf(ymx, fmaxf(fmaxf(ay[j].x, ay[j].y), fmaxf(ay[j].z, ay[j].w)));
    }

    #pragma unroll
    for (int off = 16; off > 0; off >>= 1) {
        xmn = fminf(xmn, __shfl_xor_sync(0xFFFFFFFFu, xmn, off));
        xmx = fmaxf(xmx, __shfl_xor_sync(0xFFFFFFFFu, xmx, off));
        ymn = fminf(ymn, __shfl_xor_sync(0xFFFFFFFFu, ymn, off));
        ymx = fmaxf(ymx, __shfl_xor_sync(0xFFFFFFFFu, ymx, off));
    }

    __shared__ float4 s[8];
    const int wid = threadIdx.x >> 5;
    const int lid = threadIdx.x & 31;
    if (lid == 0) s[wid] = make_float4(xmn, xmx, ymn, ymx);
    __syncthreads();
    if (threadIdx.x == 0) {
        float4 r = s[0];
        #pragma unroll
        for (int w = 1; w < 8; w++) {
            r.x = fminf(r.x, s[w].x);
            r.y = fmaxf(r.y, s[w].y);
            r.z = fminf(r.z, s[w].z);
            r.w = fmaxf(r.w, s[w].w);
        }
        g_part[b][blockIdx.x] = r;
    }
}

// K2: scatter (PDL). Each thread handles IT=16 sources as 4 groups of 4
// consecutive sources -> all payload traffic is LDG.128 (12 loads instead of 32).
constexpr int TPB = 256;
constexpr int IT  = 16;
constexpr int GRP = IT / 4;     // 4 groups of 4 sources

__global__ __launch_bounds__(TPB) void scatter_kernel(
    const float*  __restrict__ point_rates,
    const float2* __restrict__ coords,
    float*        __restrict__ out)
{
    const int b = blockIdx.y;
    float* ob = out + (size_t)b * HWSZ;

    // float4 views: coords = 2 float4 per 4 sources; rates = 1 float4 per 4.
    const float4* c4  = reinterpret_cast<const float4*>(coords);
    const float4* pr4 = reinterpret_cast<const float4*>(point_rates + (size_t)b * NS);

    // Group g of this thread covers sources [4*(base4 + g*TPB) .. +3].
    const int base4 = blockIdx.x * (TPB * GRP) + threadIdx.x;

    float2 c[IT];
    float4 rv[GRP];
    #pragma unroll
    for (int g = 0; g < GRP; g++) {
        const int i4 = base4 + g * TPB;
        float4 cA = c4[i4 * 2];        // sources 4i, 4i+1
        float4 cB = c4[i4 * 2 + 1];    // sources 4i+2, 4i+3
        c[g * 4 + 0] = make_float2(cA.x, cA.y);
        c[g * 4 + 1] = make_float2(cA.z, cA.w);
        c[g * 4 + 2] = make_float2(cB.x, cB.y);
        c[g * 4 + 3] = make_float2(cB.z, cB.w);
        rv[g] = pr4[i4];
    }

    // Wait for minmax grid completion (bounds written, out zeroed).
    cudaGridDependencySynchronize();

    // Bounds prologue: one warp reduces the SEGS(=16) partials.
    __shared__ float4 sb;
    if (threadIdx.x < 32) {
        const int lid = threadIdx.x;
        float xmn = 3.4e38f, xmx = -3.4e38f, ymn = 3.4e38f, ymx = -3.4e38f;
        if (lid < SEGS) {
            float4 p = g_part[b][lid];
            xmn = p.x; xmx = p.y; ymn = p.z; ymx = p.w;
        }
        #pragma unroll
        for (int off = 8; off > 0; off >>= 1) {
            xmn = fminf(xmn, __shfl_xor_sync(0xFFFFFFFFu, xmn, off));
            xmx = fmaxf(xmx, __shfl_xor_sync(0xFFFFFFFFu, xmx, off));
            ymn = fminf(ymn, __shfl_xor_sync(0xFFFFFFFFu, ymn, off));
            ymx = fmaxf(ymx, __shfl_xor_sync(0xFFFFFFFFu, ymx, off));
        }
        if (threadIdx.x == 0) sb = make_float4(xmn, xmx, ymn, ymx);
    }
    __syncthreads();

    const float xmin = sb.x, xmax = sb.y, ymin = sb.z, ymax = sb.w;
    const float dx = __fsub_rn(xmax, xmin);
    const float dy = __fsub_rn(ymax, ymin);

    const float* rates = reinterpret_cast<const float*>(rv);

    #pragma unroll
    for (int j = 0; j < IT; j++) {
        const bool iv = (c[j].x >= xmin) && (c[j].x <= xmax) &&
                        (c[j].y >= ymin) && (c[j].y <= ymax);
        // Match reference bit-exactly: strict IEEE rn sub/div/mul, then
        // round-half-even (== jnp.round) before clip.
        const float nx = __fdiv_rn(__fsub_rn(c[j].x, xmin), dx);
        const float ny = __fdiv_rn(__fsub_rn(c[j].y, ymin), dy);
        int px = __float2int_rn(__fmul_rn(nx, 255.0f));
        int py = __float2int_rn(__fmul_rn(ny, 255.0f));
        px = min(max(px, 0), WW - 1);
        py = min(max(py, 0), HH - 1);
        if (iv) {
            atomicAdd(&ob[py * WW + px], rates[j]);   // RED.ADD, no return
        }
    }
}

// K3: finalize (PDL). Front-batch gia loads before grid-dep sync, then
// batch-load out, multiply, store.
constexpr int MTPB  = 256;
constexpr int MIT   = 4;
constexpr int MBLKS = (BB * HWSZ / 4) / (MTPB * MIT);   // 512 blocks

__global__ __launch_bounds__(MTPB) void mul_kernel(const float4* __restrict__ gia,
                                                   float4* __restrict__ out)
{
    const int i0 = blockIdx.x * MTPB + threadIdx.x;
    const int stride = MBLKS * MTPB;                     // 131072

    float4 g[MIT];
    #pragma unroll
    for (int j = 0; j < MIT; j++) g[j] = gia[i0 + j * stride];

    cudaGridDependencySynchronize();

    float4 o[MIT];
    #pragma unroll
    for (int j = 0; j < MIT; j++) o[j] = out[i0 + j * stride];

    #pragma unroll
    for (int j = 0; j < MIT; j++) {
        o[j].x = __fmul_rn(o[j].x, g[j].x);
        o[j].y = __fmul_rn(o[j].y, g[j].y);
        o[j].z = __fmul_rn(o[j].z, g[j].z);
        o[j].w = __fmul_rn(o[j].w, g[j].w);
        out[i0 + j * stride] = o[j];
    }
}

extern "C" void kernel_launch(void* const* d_in, const int* in_sizes, int n_in,
                              void* d_out, int out_size)
{
    const float*  point_rates = (const float*)d_in[0];   // (B, NS)
    const float*  spatial     = (const float*)d_in[1];   // (B, 2, H, W)
    const float*  gia         = (const float*)d_in[2];   // (B, H, W)
    const float2* coords      = (const float2*)d_in[3];  // (NS, 2)
    float* out = (float*)d_out;                          // (B, 1, H, W)

    // K1: minmax partials + output zeroing
    dim3 mg(SEGS, BB);
    minmax_kernel<<<mg, 256>>>(spatial, (float4*)out);

    cudaLaunchAttribute pdl[1];
    pdl[0].id = cudaLaunchAttributeProgrammaticStreamSerialization;
    pdl[0].val.programmaticStreamSerializationAllowed = 1;

    // K2: scatter with PDL (payload loads overlap minmax drain)
    {
        cudaLaunchConfig_t cfg = {};
        cfg.gridDim = dim3(NS / (TPB * IT), BB);
        cfg.blockDim = dim3(TPB);
        cfg.stream = 0;
        cfg.attrs = pdl;
        cfg.numAttrs = 1;
        cudaLaunchKernelEx(&cfg, scatter_kernel, point_rates, coords, out);
    }

    // K3: mul with PDL (gia prefetch overlaps scatter drain)
    {
        cudaLaunchConfig_t cfg = {};
        cfg.gridDim = dim3(MBLKS);
        cfg.blockDim = dim3(MTPB);
        cfg.stream = 0;
        cfg.attrs = pdl;
        cfg.numAttrs = 1;
        cudaLaunchKernelEx(&cfg, mul_kernel, (const float4*)gia, (float4*)out);
    }
}